// round 7
// baseline (speedup 1.0000x reference)
#include <cuda_runtime.h>
#include <cuda_bf16.h>
#include <cuda_fp8.h>
#include <math.h>
#include <stdint.h>

#define NROWS 4096
#define HALF_N 2048
#define DD 512
#define INV_TAU 5.0f

#define ACH 8192                   // A chunk: 64 rows x 128B
#define BCH 16384                  // B stage: 128 rows x 128B
#define OFFB 32768                 // B ring after 4 resident A chunks
#define SMEM_DYN (32768 + 3 * 16384 + 1024)
#define GRID_GEMM 288

// ---- device-global scratch ----
__device__ __align__(16) uint8_t g_zn_f8[NROWS * DD];
__device__ float g_row_sum[NROWS];
__device__ float g_pos_acc;
__device__ unsigned int g_ctr;

// ============================================================
// K1: normalize rows of concat(z1,z2) -> e4m3; zero accumulators
// ============================================================
__global__ void k_normalize(const float* __restrict__ z1, const float* __restrict__ z2) {
    int row = blockIdx.x;
    const float* src = (row < HALF_N) ? (z1 + (size_t)row * DD)
                                      : (z2 + (size_t)(row - HALF_N) * DD);
    int t = threadIdx.x;
    float4 v = ((const float4*)src)[t];
    float ss = v.x * v.x + v.y * v.y + v.z * v.z + v.w * v.w;
    #pragma unroll
    for (int o = 16; o; o >>= 1) ss += __shfl_xor_sync(0xffffffffu, ss, o);

    __shared__ float warp_ss[4];
    __shared__ float s_inv;
    if ((t & 31) == 0) warp_ss[t >> 5] = ss;
    __syncthreads();
    if (t == 0) {
        float tot = warp_ss[0] + warp_ss[1] + warp_ss[2] + warp_ss[3];
        s_inv = 1.0f / fmaxf(sqrtf(tot), 1e-8f);
        g_row_sum[row] = 0.0f;
        if (row == 0) { g_pos_acc = 0.0f; g_ctr = 0u; }
    }
    __syncthreads();
    float inv = s_inv;
    __nv_fp8x2_storage_t p0 =
        __nv_cvt_float2_to_fp8x2(make_float2(v.x * inv, v.y * inv), __NV_SATFINITE, __NV_E4M3);
    __nv_fp8x2_storage_t p1 =
        __nv_cvt_float2_to_fp8x2(make_float2(v.z * inv, v.w * inv), __NV_SATFINITE, __NV_E4M3);
    uint32_t pk = (uint32_t)p0 | ((uint32_t)p1 << 16);
    ((uint32_t*)(g_zn_f8 + (size_t)row * DD))[t] = pk;
}

// ============================================================
// K2: persistent fp8 GEMM, 64x128 CTA tiles, 2 CTAs/SM
// ============================================================
__device__ __forceinline__ void cp_async16(uint32_t saddr, const void* gptr) {
    asm volatile("cp.async.cg.shared.global [%0], [%1], 16;\n" :: "r"(saddr), "l"(gptr));
}
__device__ __forceinline__ void ldm_x4(uint32_t& r0, uint32_t& r1, uint32_t& r2, uint32_t& r3,
                                       uint32_t addr) {
    asm volatile("ldmatrix.sync.aligned.m8n8.x4.shared.b16 {%0,%1,%2,%3}, [%4];\n"
                 : "=r"(r0), "=r"(r1), "=r"(r2), "=r"(r3) : "r"(addr));
}
__device__ __forceinline__ void mma_fp8(float* c, uint32_t a0, uint32_t a1, uint32_t a2,
                                        uint32_t a3, uint32_t b0, uint32_t b1) {
    asm volatile("mma.sync.aligned.m16n8k32.row.col.f32.e4m3.e4m3.f32 "
                 "{%0,%1,%2,%3}, {%4,%5,%6,%7}, {%8,%9}, {%0,%1,%2,%3};\n"
                 : "+f"(c[0]), "+f"(c[1]), "+f"(c[2]), "+f"(c[3])
                 : "r"(a0), "r"(a1), "r"(a2), "r"(a3), "r"(b0), "r"(b1));
}

__global__ void __launch_bounds__(256, 2) k_persist(float* __restrict__ out) {
    extern __shared__ uint8_t dsm_raw[];
    __shared__ float s_red[8];
    __shared__ int s_last;
    uint32_t raw_u = (uint32_t)__cvta_generic_to_shared(dsm_raw);
    uint32_t sm_u = (raw_u + 1023u) & ~1023u;

    // ---- CTA -> (bm, half, group-of-4-bn) ----
    int b2 = blockIdx.x >> 1;
    int hh = blockIdx.x & 1;                  // which 64-row half of the A band
    int idx = b2, bm = 0, gj = 0;
    #pragma unroll 1
    for (bm = 0; bm < 32; bm++) {
        int G = (32 - bm + 3) >> 2;
        if (idx < G) { gj = idx; break; }
        idx -= G;
    }
    int bn0 = bm + gj * 4;
    int n_tiles = 32 - bn0; if (n_tiles > 4) n_tiles = 4;
    int total = n_tiles * 4;
    int rowBase = bm * 128 + hh * 64;         // global first A row of this CTA

    int tid = threadIdx.x;
    int lane = tid & 31, warp = tid >> 5;
    int wm = warp >> 2, wn = warp & 3;        // 2x4 warp grid, 32x32 warp tiles

    // ---- loader geometry (B stage: 1024 x 16B, 4 per thread) ----
    int lr = tid >> 3, lc = tid & 7;          // 32 rows per pass
    const uint8_t* gBbase = g_zn_f8 + lc * 16;

    // ---- prologue: A resident (32KB = 2048 x 16B, 8 per thread) ----
    #pragma unroll
    for (int i = 0; i < 8; i++) {
        int u = tid + i * 256;
        int c = u >> 9, w = u & 511, r = w >> 3, cc = w & 7;
        uint32_t dst = sm_u + c * ACH + (uint32_t)(r * 128 + ((cc ^ (r & 7)) << 4));
        cp_async16(dst, g_zn_f8 + ((size_t)(rowBase + r) << 9) + c * 128 + cc * 16);
    }
    asm volatile("cp.async.commit_group;\n");
    // first 2 B stages (slots 0,1)
    #pragma unroll
    for (int g = 0; g < 2; g++) {
        int bnB = (bn0 + (g >> 2)) * 128;
        int kB = (g & 3) * 128;
        #pragma unroll
        for (int i = 0; i < 4; i++) {
            int r = lr + i * 32;
            uint32_t dst = sm_u + OFFB + g * BCH + (uint32_t)(r * 128 + ((lc ^ (r & 7)) << 4));
            cp_async16(dst, gBbase + ((size_t)(bnB + r) << 9) + kB);
        }
        asm volatile("cp.async.commit_group;\n");
    }

    // ---- precomputed within-stage ldsm offsets ----
    int rA0 = wm * 32 + (lane & 15), rA1 = rA0 + 16;                 // A rows < 64
    int rB0 = wn * 32 + (lane & 7) + ((lane >> 4) << 3), rB1 = rB0 + 16;
    uint32_t cA = (uint32_t)(lane >> 4);
    uint32_t cB = (uint32_t)((lane >> 3) & 1);
    uint32_t adA0[4], adA1[4], adB0[4], adB1[4];
    #pragma unroll
    for (int kk = 0; kk < 4; kk++) {
        adA0[kk] = (uint32_t)(rA0 * 128) + ((((uint32_t)(kk * 2) + cA) ^ (uint32_t)(rA0 & 7)) << 4);
        adA1[kk] = (uint32_t)(rA1 * 128) + ((((uint32_t)(kk * 2) + cA) ^ (uint32_t)(rA1 & 7)) << 4);
        adB0[kk] = (uint32_t)(rB0 * 128) + ((((uint32_t)(kk * 2) + cB) ^ (uint32_t)(rB0 & 7)) << 4);
        adB1[kk] = (uint32_t)(rB1 * 128) + ((((uint32_t)(kk * 2) + cB) ^ (uint32_t)(rB1 & 7)) << 4);
    }

    float acc[2][4][4];
    #pragma unroll
    for (int i = 0; i < 2; i++)
        #pragma unroll
        for (int j = 0; j < 4; j++)
            #pragma unroll
            for (int k = 0; k < 4; k++) acc[i][j][k] = 0.0f;

    // ---- flat stage loop: tile t=f>>2, k-chunk c=f&3, B slot f%3 ----
    int sCur = 0, sPre = 2;
    #pragma unroll 1
    for (int f = 0; f < total; f++) {
        if (f < total - 1) asm volatile("cp.async.wait_group 1;\n");
        else               asm volatile("cp.async.wait_group 0;\n");
        __syncthreads();
        int g = f + 2;
        if (g < total) {
            int bnB = (bn0 + (g >> 2)) * 128;
            int kB = (g & 3) * 128;
            #pragma unroll
            for (int i = 0; i < 4; i++) {
                int r = lr + i * 32;
                uint32_t dst = sm_u + OFFB + sPre * BCH + (uint32_t)(r * 128 + ((lc ^ (r & 7)) << 4));
                cp_async16(dst, gBbase + ((size_t)(bnB + r) << 9) + kB);
            }
            asm volatile("cp.async.commit_group;\n");
        }

        uint32_t soA = sm_u + (uint32_t)((f & 3) * ACH);
        uint32_t soB = sm_u + OFFB + (uint32_t)(sCur * BCH);
        #pragma unroll
        for (int kk = 0; kk < 4; kk++) {
            uint32_t a[2][4], b[4][2];
            ldm_x4(a[0][0], a[0][1], a[0][2], a[0][3], soA + adA0[kk]);
            ldm_x4(a[1][0], a[1][1], a[1][2], a[1][3], soA + adA1[kk]);
            ldm_x4(b[0][0], b[0][1], b[1][0], b[1][1], soB + adB0[kk]);
            ldm_x4(b[2][0], b[2][1], b[3][0], b[3][1], soB + adB1[kk]);
            #pragma unroll
            for (int mt = 0; mt < 2; mt++)
                #pragma unroll
                for (int nt = 0; nt < 4; nt++)
                    mma_fp8(acc[mt][nt], a[mt][0], a[mt][1], a[mt][2], a[mt][3],
                            b[nt][0], b[nt][1]);
        }
        if (++sCur == 3) sCur = 0;
        if (++sPre == 3) sPre = 0;

        if ((f & 3) == 3) {
            // ---- per-tile epilogue (barrier-free) ----
            int bn = bn0 + (f >> 2);
            bool diag = (bn == bm);
            bool isPos = (bn == bm + 16);
            float rowPart[2][2], colPart[4][2], pos_l = 0.0f;
            #pragma unroll
            for (int i = 0; i < 2; i++) rowPart[i][0] = rowPart[i][1] = 0.0f;
            #pragma unroll
            for (int i = 0; i < 4; i++) colPart[i][0] = colPart[i][1] = 0.0f;

            #pragma unroll
            for (int mt = 0; mt < 2; mt++)
                #pragma unroll
                for (int nt = 0; nt < 4; nt++)
                    #pragma unroll
                    for (int j = 0; j < 4; j++) {
                        float lg = acc[mt][nt][j] * INV_TAU;
                        float e = __expf(lg);
                        if (diag || isPos) {
                            int rl = hh * 64 + wm * 32 + mt * 16 + (lane >> 2) + (j >> 1) * 8;
                            int cl = wn * 32 + nt * 8 + (lane & 3) * 2 + (j & 1);
                            if (rl == cl) {
                                if (diag) e = 0.0f;
                                else pos_l += lg;
                            }
                        }
                        rowPart[mt][j >> 1] += e;
                        colPart[nt][j & 1] += e;
                        acc[mt][nt][j] = 0.0f;
                    }

            #pragma unroll
            for (int mt = 0; mt < 2; mt++)
                #pragma unroll
                for (int q = 0; q < 2; q++) {
                    float v = rowPart[mt][q];
                    v += __shfl_xor_sync(0xffffffffu, v, 1);
                    v += __shfl_xor_sync(0xffffffffu, v, 2);
                    if ((lane & 3) == 0)
                        atomicAdd(&g_row_sum[rowBase + wm * 32 + mt * 16 + (lane >> 2) + q * 8], v);
                }
            if (!diag) {
                #pragma unroll
                for (int nt = 0; nt < 4; nt++)
                    #pragma unroll
                    for (int p = 0; p < 2; p++) {
                        float v = colPart[nt][p];
                        v += __shfl_xor_sync(0xffffffffu, v, 4);
                        v += __shfl_xor_sync(0xffffffffu, v, 8);
                        v += __shfl_xor_sync(0xffffffffu, v, 16);
                        if (lane < 4)
                            atomicAdd(&g_row_sum[bn * 128 + wn * 32 + nt * 8 + (lane & 3) * 2 + p], v);
                    }
            }
            if (isPos) {
                #pragma unroll
                for (int o = 16; o; o >>= 1) pos_l += __shfl_xor_sync(0xffffffffu, pos_l, o);
                if (lane == 0) atomicAdd(&g_pos_acc, pos_l);
            }
        }
    }

    // ---- finalize: last CTA computes the loss ----
    __threadfence();
    __syncthreads();
    if (tid == 0) {
        unsigned prev = atomicAdd(&g_ctr, 1u);
        s_last = (prev == (unsigned)(GRID_GEMM - 1)) ? 1 : 0;
    }
    __syncthreads();
    if (s_last) {
        __threadfence();
        float ls = 0.0f;
        #pragma unroll 1
        for (int r = tid; r < NROWS; r += 256) ls += logf(__ldcg(&g_row_sum[r]));
        #pragma unroll
        for (int o = 16; o; o >>= 1) ls += __shfl_xor_sync(0xffffffffu, ls, o);
        if (lane == 0) s_red[warp] = ls;
        __syncthreads();
        if (tid == 0) {
            float tot = 0.0f;
            #pragma unroll
            for (int i = 0; i < 8; i++) tot += s_red[i];
            float pos2 = __ldcg(&g_pos_acc) * 2.0f;
            out[0] = (tot - pos2) * (1.0f / (float)NROWS);
        }
    }
}

extern "C" void kernel_launch(void* const* d_in, const int* in_sizes, int n_in,
                              void* d_out, int out_size) {
    const float* z1 = (const float*)d_in[0];
    const float* z2 = (const float*)d_in[1];
    float* out = (float*)d_out;
    cudaFuncSetAttribute(k_persist, cudaFuncAttributeMaxDynamicSharedMemorySize, SMEM_DYN);
    k_normalize<<<NROWS, 128>>>(z1, z2);
    k_persist<<<GRID_GEMM, 256, SMEM_DYN>>>(out);
}

// round 8
// speedup vs baseline: 1.3279x; 1.3279x over previous
#include <cuda_runtime.h>
#include <cuda_bf16.h>
#include <math.h>
#include <stdint.h>

#define NROWS 4096
#define HALF_N 2048
#define DD 512

#define CH 16384                   // one 128-row x 128B chunk
#define OFFB 65536                 // B ring after 4 resident A chunks
#define SMEM_DYN (131072 + 1024)
#define GRID_GEMM 144

// ---- device-global scratch ----
__device__ __align__(16) uint8_t g_q8[NROWS * DD];   // int8 quantized rows
__device__ float g_beta[NROWS];                      // sqrt(5)/|q_row|
__device__ float g_row_sum[NROWS];
__device__ float g_pos_acc;
__device__ unsigned int g_ctr;

// ============================================================
// K1: normalize -> int8 quantize; per-row beta; zero accumulators
// ============================================================
__global__ void k_normalize(const float* __restrict__ z1, const float* __restrict__ z2) {
    int row = blockIdx.x;
    const float* src = (row < HALF_N) ? (z1 + (size_t)row * DD)
                                      : (z2 + (size_t)(row - HALF_N) * DD);
    int t = threadIdx.x;
    float4 v = ((const float4*)src)[t];
    float ss = v.x * v.x + v.y * v.y + v.z * v.z + v.w * v.w;
    #pragma unroll
    for (int o = 16; o; o >>= 1) ss += __shfl_xor_sync(0xffffffffu, ss, o);

    __shared__ float warp_ss[4];
    __shared__ float s_inv;
    __shared__ int warp_qs[4];
    if ((t & 31) == 0) warp_ss[t >> 5] = ss;
    __syncthreads();
    if (t == 0) {
        float tot = warp_ss[0] + warp_ss[1] + warp_ss[2] + warp_ss[3];
        s_inv = 127.0f / fmaxf(sqrtf(tot), 1e-8f);
        g_row_sum[row] = 0.0f;
        if (row == 0) { g_pos_acc = 0.0f; g_ctr = 0u; }
    }
    __syncthreads();
    float inv = s_inv;
    int qa = __float2int_rn(fminf(fmaxf(v.x * inv, -127.0f), 127.0f));
    int qb = __float2int_rn(fminf(fmaxf(v.y * inv, -127.0f), 127.0f));
    int qc = __float2int_rn(fminf(fmaxf(v.z * inv, -127.0f), 127.0f));
    int qd = __float2int_rn(fminf(fmaxf(v.w * inv, -127.0f), 127.0f));
    uint32_t pk = (uint32_t)(qa & 0xFF) | ((uint32_t)(qb & 0xFF) << 8) |
                  ((uint32_t)(qc & 0xFF) << 16) | ((uint32_t)(qd & 0xFF) << 24);
    ((uint32_t*)(g_q8 + (size_t)row * DD))[t] = pk;

    int qs = qa * qa + qb * qb + qc * qc + qd * qd;
    #pragma unroll
    for (int o = 16; o; o >>= 1) qs += __shfl_xor_sync(0xffffffffu, qs, o);
    if ((t & 31) == 0) warp_qs[t >> 5] = qs;
    __syncthreads();
    if (t == 0) {
        int tq = warp_qs[0] + warp_qs[1] + warp_qs[2] + warp_qs[3];
        g_beta[row] = sqrtf(5.0f) * rsqrtf((float)tq);   // beta_r*beta_c = 5/(|qr||qc|)
    }
}

// ============================================================
// K2: persistent int8 IMMA GEMM, A resident, B ring, fused epilogue
// ============================================================
__device__ __forceinline__ void cp_async16(uint32_t saddr, const void* gptr) {
    asm volatile("cp.async.cg.shared.global [%0], [%1], 16;\n" :: "r"(saddr), "l"(gptr));
}
__device__ __forceinline__ void ldm_x4(uint32_t& r0, uint32_t& r1, uint32_t& r2, uint32_t& r3,
                                       uint32_t addr) {
    asm volatile("ldmatrix.sync.aligned.m8n8.x4.shared.b16 {%0,%1,%2,%3}, [%4];\n"
                 : "=r"(r0), "=r"(r1), "=r"(r2), "=r"(r3) : "r"(addr));
}
__device__ __forceinline__ void mma_s8(int* c, uint32_t a0, uint32_t a1, uint32_t a2,
                                       uint32_t a3, uint32_t b0, uint32_t b1) {
    asm volatile("mma.sync.aligned.m16n8k32.row.col.s32.s8.s8.s32 "
                 "{%0,%1,%2,%3}, {%4,%5,%6,%7}, {%8,%9}, {%0,%1,%2,%3};\n"
                 : "+r"(c[0]), "+r"(c[1]), "+r"(c[2]), "+r"(c[3])
                 : "r"(a0), "r"(a1), "r"(a2), "r"(a3), "r"(b0), "r"(b1));
}

__global__ void __launch_bounds__(256, 1) k_persist(float* __restrict__ out) {
    extern __shared__ uint8_t dsm_raw[];
    __shared__ float s_red[8];
    __shared__ int s_last;
    uint32_t raw_u = (uint32_t)__cvta_generic_to_shared(dsm_raw);
    uint32_t sm_u = (raw_u + 1023u) & ~1023u;

    // ---- CTA -> (bm, group-of-4-bn) ----
    int idx = blockIdx.x, bm = 0, gj = 0;
    #pragma unroll 1
    for (bm = 0; bm < 32; bm++) {
        int G = (32 - bm + 3) >> 2;
        if (idx < G) { gj = idx; break; }
        idx -= G;
    }
    int bn0 = bm + gj * 4;
    int n_tiles = 32 - bn0; if (n_tiles > 4) n_tiles = 4;
    int total = n_tiles * 4;

    int tid = threadIdx.x;
    int lane = tid & 31, warp = tid >> 5;
    int wm = warp >> 2, wn = warp & 3;        // 2x4 warp grid, 64x32 warp tiles

    // ---- loader geometry (B stage: 4 x 16B per thread) ----
    int lr = tid >> 3, lcc = tid & 7;
    uint32_t wB = sm_u + OFFB + (uint32_t)(lr * 128 + ((lcc ^ (lr & 7)) << 4));
    const uint8_t* gB = g_q8 + lcc * 16;

    // ---- prologue: A resident (64KB, 16 x 16B per thread) ----
    #pragma unroll
    for (int i = 0; i < 16; i++) {
        int u = tid + i * 256;
        int c = u >> 10, w = u & 1023, r = w >> 3, cc = w & 7;
        uint32_t dst = sm_u + c * CH + (uint32_t)(r * 128 + ((cc ^ (r & 7)) << 4));
        cp_async16(dst, g_q8 + ((size_t)(bm * 128 + r) << 9) + c * 128 + cc * 16);
    }
    asm volatile("cp.async.commit_group;\n");
    #pragma unroll
    for (int g = 0; g < 3; g++) {             // first 3 B stages
        int bnB = (bn0 + (g >> 2)) * 128;
        int kB = (g & 3) * 128;
        #pragma unroll
        for (int i = 0; i < 4; i++)
            cp_async16(wB + (uint32_t)((g & 3) * CH) + (uint32_t)(i * 4096),
                       gB + ((size_t)(bnB + lr + i * 32) << 9) + kB);
        asm volatile("cp.async.commit_group;\n");
    }

    // ---- precomputed ldsm addresses [kk] ----
    int rB0 = wn * 32 + (lane & 7) + ((lane >> 4) << 3), rB1 = rB0 + 16;
    uint32_t cA = (uint32_t)(lane >> 4);
    uint32_t cB = (uint32_t)((lane >> 3) & 1);
    uint32_t adA[4][4], adB0[4], adB1[4];
    #pragma unroll
    for (int mt = 0; mt < 4; mt++) {
        int rA = wm * 64 + mt * 16 + (lane & 15);
        #pragma unroll
        for (int kk = 0; kk < 4; kk++)
            adA[mt][kk] = (uint32_t)(rA * 128) +
                          ((((uint32_t)(kk * 2) + cA) ^ (uint32_t)(rA & 7)) << 4);
    }
    #pragma unroll
    for (int kk = 0; kk < 4; kk++) {
        adB0[kk] = (uint32_t)(rB0 * 128) + OFFB +
                   ((((uint32_t)(kk * 2) + cB) ^ (uint32_t)(rB0 & 7)) << 4);
        adB1[kk] = (uint32_t)(rB1 * 128) + OFFB +
                   ((((uint32_t)(kk * 2) + cB) ^ (uint32_t)(rB1 & 7)) << 4);
    }

    // ---- per-thread row betas (hoisted; rows fixed per thread) ----
    float betaR[4][2];
    #pragma unroll
    for (int mt = 0; mt < 4; mt++)
        #pragma unroll
        for (int h = 0; h < 2; h++)
            betaR[mt][h] = __ldg(&g_beta[bm * 128 + wm * 64 + mt * 16 + (lane >> 2) + h * 8]);

    int acc[4][4][4];
    #pragma unroll
    for (int i = 0; i < 4; i++)
        #pragma unroll
        for (int j = 0; j < 4; j++)
            #pragma unroll
            for (int k = 0; k < 4; k++) acc[i][j][k] = 0;

    // ---- flat stage loop: stage f = tile (f>>2), chunk/slot (f&3) ----
    #pragma unroll 1
    for (int f = 0; f < total; f++) {
        int rem = total - 1 - f;
        if (rem >= 2)      asm volatile("cp.async.wait_group 2;\n");
        else if (rem == 1) asm volatile("cp.async.wait_group 1;\n");
        else               asm volatile("cp.async.wait_group 0;\n");
        __syncthreads();
        int g = f + 3;
        if (g < total) {
            int bnB = (bn0 + (g >> 2)) * 128;
            int kB = (g & 3) * 128;
            #pragma unroll
            for (int i = 0; i < 4; i++)
                cp_async16(wB + (uint32_t)((g & 3) * CH) + (uint32_t)(i * 4096),
                           gB + ((size_t)(bnB + lr + i * 32) << 9) + kB);
            asm volatile("cp.async.commit_group;\n");
        }

        uint32_t so = sm_u + (uint32_t)((f & 3) * CH);
        #pragma unroll
        for (int kk = 0; kk < 4; kk++) {
            uint32_t a[4][4], b[4][2];
            #pragma unroll
            for (int mt = 0; mt < 4; mt++)
                ldm_x4(a[mt][0], a[mt][1], a[mt][2], a[mt][3], so + adA[mt][kk]);
            ldm_x4(b[0][0], b[0][1], b[1][0], b[1][1], so + adB0[kk]);
            ldm_x4(b[2][0], b[2][1], b[3][0], b[3][1], so + adB1[kk]);
            #pragma unroll
            for (int mt = 0; mt < 4; mt++)
                #pragma unroll
                for (int nt = 0; nt < 4; nt++)
                    mma_s8(acc[mt][nt], a[mt][0], a[mt][1], a[mt][2], a[mt][3],
                           b[nt][0], b[nt][1]);
        }

        if ((f & 3) == 3) {
            // ---- per-tile epilogue (barrier-free) ----
            int bn = bn0 + (f >> 2);
            bool diag = (bn == bm);
            bool isPos = (bn == bm + 16);
            float betaC[4][2];
            #pragma unroll
            for (int nt = 0; nt < 4; nt++)
                #pragma unroll
                for (int p = 0; p < 2; p++)
                    betaC[nt][p] = __ldg(&g_beta[bn * 128 + wn * 32 + nt * 8 + (lane & 3) * 2 + p]);

            float rowPart[4][2], colPart[4][2], pos_l = 0.0f;
            #pragma unroll
            for (int i = 0; i < 4; i++) {
                rowPart[i][0] = rowPart[i][1] = 0.0f;
                colPart[i][0] = colPart[i][1] = 0.0f;
            }
            #pragma unroll
            for (int mt = 0; mt < 4; mt++)
                #pragma unroll
                for (int nt = 0; nt < 4; nt++)
                    #pragma unroll
                    for (int j = 0; j < 4; j++) {
                        float lg = __int2float_rn(acc[mt][nt][j]) *
                                   betaR[mt][j >> 1] * betaC[nt][j & 1];
                        float e = __expf(lg);
                        if (diag || isPos) {
                            int rl = wm * 64 + mt * 16 + (lane >> 2) + (j >> 1) * 8;
                            int cl = wn * 32 + nt * 8 + (lane & 3) * 2 + (j & 1);
                            if (rl == cl) {
                                if (diag) e = 0.0f;
                                else pos_l += lg;
                            }
                        }
                        rowPart[mt][j >> 1] += e;
                        colPart[nt][j & 1] += e;
                        acc[mt][nt][j] = 0;
                    }

            #pragma unroll
            for (int mt = 0; mt < 4; mt++)
                #pragma unroll
                for (int h = 0; h < 2; h++) {
                    float v = rowPart[mt][h];
                    v += __shfl_xor_sync(0xffffffffu, v, 1);
                    v += __shfl_xor_sync(0xffffffffu, v, 2);
                    if ((lane & 3) == 0)
                        atomicAdd(&g_row_sum[bm * 128 + wm * 64 + mt * 16 + (lane >> 2) + h * 8], v);
                }
            if (!diag) {
                #pragma unroll
                for (int nt = 0; nt < 4; nt++)
                    #pragma unroll
                    for (int p = 0; p < 2; p++) {
                        float v = colPart[nt][p];
                        v += __shfl_xor_sync(0xffffffffu, v, 4);
                        v += __shfl_xor_sync(0xffffffffu, v, 8);
                        v += __shfl_xor_sync(0xffffffffu, v, 16);
                        if (lane < 4)
                            atomicAdd(&g_row_sum[bn * 128 + wn * 32 + nt * 8 + (lane & 3) * 2 + p], v);
                    }
            }
            if (isPos) {
                #pragma unroll
                for (int o = 16; o; o >>= 1) pos_l += __shfl_xor_sync(0xffffffffu, pos_l, o);
                if (lane == 0) atomicAdd(&g_pos_acc, pos_l);
            }
        }
    }

    // ---- finalize: last CTA computes the loss ----
    __threadfence();
    __syncthreads();
    if (tid == 0) {
        unsigned prev = atomicAdd(&g_ctr, 1u);
        s_last = (prev == (unsigned)(GRID_GEMM - 1)) ? 1 : 0;
    }
    __syncthreads();
    if (s_last) {
        __threadfence();
        float ls = 0.0f;
        #pragma unroll 1
        for (int r = tid; r < NROWS; r += 256) ls += logf(__ldcg(&g_row_sum[r]));
        #pragma unroll
        for (int o = 16; o; o >>= 1) ls += __shfl_xor_sync(0xffffffffu, ls, o);
        if (lane == 0) s_red[warp] = ls;
        __syncthreads();
        if (tid == 0) {
            float tot = 0.0f;
            #pragma unroll
            for (int i = 0; i < 8; i++) tot += s_red[i];
            float pos2 = __ldcg(&g_pos_acc) * 2.0f;
            out[0] = (tot - pos2) * (1.0f / (float)NROWS);
        }
    }
}

extern "C" void kernel_launch(void* const* d_in, const int* in_sizes, int n_in,
                              void* d_out, int out_size) {
    const float* z1 = (const float*)d_in[0];
    const float* z2 = (const float*)d_in[1];
    float* out = (float*)d_out;
    cudaFuncSetAttribute(k_persist, cudaFuncAttributeMaxDynamicSharedMemorySize, SMEM_DYN);
    k_normalize<<<NROWS, 128>>>(z1, z2);
    k_persist<<<GRID_GEMM, 256, SMEM_DYN>>>(out);
}

// round 11
// speedup vs baseline: 1.3382x; 1.0078x over previous
#include <cuda_runtime.h>
#include <cuda_bf16.h>
#include <math.h>
#include <stdint.h>

#define NROWS 4096
#define HALF_N 2048
#define DD 512

#define ACH 8192                   // A chunk: 64 rows x 128B
#define BCH 16384                  // B stage: 128 rows x 128B
#define OFFB 32768                 // B ring after 4 resident A chunks
#define SMEM_DYN (32768 + 3 * 16384 + 1024)
#define GRID_GEMM 288

// ---- device-global scratch ----
__device__ __align__(16) uint8_t g_q8[NROWS * DD];   // int8 quantized rows
__device__ float g_beta[NROWS];                      // sqrt(5)/|q_row|
__device__ float g_row_sum[NROWS];
__device__ float g_pos_acc;
__device__ unsigned int g_ctr;

// ============================================================
// K1: normalize -> int8 quantize; per-row beta; zero accumulators
// ============================================================
__global__ void k_normalize(const float* __restrict__ z1, const float* __restrict__ z2) {
    int row = blockIdx.x;
    const float* src = (row < HALF_N) ? (z1 + (size_t)row * DD)
                                      : (z2 + (size_t)(row - HALF_N) * DD);
    int t = threadIdx.x;
    float4 v = ((const float4*)src)[t];
    float ss = v.x * v.x + v.y * v.y + v.z * v.z + v.w * v.w;
    #pragma unroll
    for (int o = 16; o; o >>= 1) ss += __shfl_xor_sync(0xffffffffu, ss, o);

    __shared__ float warp_ss[4];
    __shared__ float s_inv;
    __shared__ int warp_qs[4];
    if ((t & 31) == 0) warp_ss[t >> 5] = ss;
    __syncthreads();
    if (t == 0) {
        float tot = warp_ss[0] + warp_ss[1] + warp_ss[2] + warp_ss[3];
        s_inv = 127.0f / fmaxf(sqrtf(tot), 1e-8f);
        g_row_sum[row] = 0.0f;
        if (row == 0) { g_pos_acc = 0.0f; g_ctr = 0u; }
    }
    __syncthreads();
    float inv = s_inv;
    int qa = __float2int_rn(fminf(fmaxf(v.x * inv, -127.0f), 127.0f));
    int qb = __float2int_rn(fminf(fmaxf(v.y * inv, -127.0f), 127.0f));
    int qc = __float2int_rn(fminf(fmaxf(v.z * inv, -127.0f), 127.0f));
    int qd = __float2int_rn(fminf(fmaxf(v.w * inv, -127.0f), 127.0f));
    uint32_t pk = (uint32_t)(qa & 0xFF) | ((uint32_t)(qb & 0xFF) << 8) |
                  ((uint32_t)(qc & 0xFF) << 16) | ((uint32_t)(qd & 0xFF) << 24);
    ((uint32_t*)(g_q8 + (size_t)row * DD))[t] = pk;

    int qs = qa * qa + qb * qb + qc * qc + qd * qd;
    #pragma unroll
    for (int o = 16; o; o >>= 1) qs += __shfl_xor_sync(0xffffffffu, qs, o);
    if ((t & 31) == 0) warp_qs[t >> 5] = qs;
    __syncthreads();
    if (t == 0) {
        int tq = warp_qs[0] + warp_qs[1] + warp_qs[2] + warp_qs[3];
        g_beta[row] = sqrtf(5.0f) * rsqrtf((float)tq);
    }
}

// ============================================================
// K2: persistent int8 IMMA GEMM, 64x128 tiles, 2 CTAs/SM
// ============================================================
__device__ __forceinline__ void cp_async16(uint32_t saddr, const void* gptr) {
    asm volatile("cp.async.cg.shared.global [%0], [%1], 16;\n" :: "r"(saddr), "l"(gptr));
}
__device__ __forceinline__ void ldm_x4(uint32_t& r0, uint32_t& r1, uint32_t& r2, uint32_t& r3,
                                       uint32_t addr) {
    asm volatile("ldmatrix.sync.aligned.m8n8.x4.shared.b16 {%0,%1,%2,%3}, [%4];\n"
                 : "=r"(r0), "=r"(r1), "=r"(r2), "=r"(r3) : "r"(addr));
}
__device__ __forceinline__ void mma_s8(int* c, uint32_t a0, uint32_t a1, uint32_t a2,
                                       uint32_t a3, uint32_t b0, uint32_t b1) {
    asm volatile("mma.sync.aligned.m16n8k32.row.col.s32.s8.s8.s32 "
                 "{%0,%1,%2,%3}, {%4,%5,%6,%7}, {%8,%9}, {%0,%1,%2,%3};\n"
                 : "+r"(c[0]), "+r"(c[1]), "+r"(c[2]), "+r"(c[3])
                 : "r"(a0), "r"(a1), "r"(a2), "r"(a3), "r"(b0), "r"(b1));
}

__global__ void __launch_bounds__(256, 2) k_persist(float* __restrict__ out) {
    extern __shared__ uint8_t dsm_raw[];
    __shared__ float s_red[8];
    __shared__ int s_last;
    uint32_t raw_u = (uint32_t)__cvta_generic_to_shared(dsm_raw);
    uint32_t sm_u = (raw_u + 1023u) & ~1023u;

    // ---- CTA -> (bm, half, group-of-4-bn) ----
    int b2 = blockIdx.x >> 1;
    int hh = blockIdx.x & 1;
    int idx = b2, bm = 0, gj = 0;
    #pragma unroll 1
    for (bm = 0; bm < 32; bm++) {
        int G = (32 - bm + 3) >> 2;
        if (idx < G) { gj = idx; break; }
        idx -= G;
    }
    int bn0 = bm + gj * 4;
    int n_tiles = 32 - bn0; if (n_tiles > 4) n_tiles = 4;
    int total = n_tiles * 4;
    int rowBase = bm * 128 + hh * 64;

    int tid = threadIdx.x;
    int lane = tid & 31, warp = tid >> 5;
    int wm = warp >> 2, wn = warp & 3;        // 2x4 warp grid, 32x32 warp tiles

    // ---- loader geometry ----
    int lr = tid >> 3, lcc = tid & 7;
    const uint8_t* gB = g_q8 + lcc * 16;

    // ---- prologue: A resident (32KB, 8 x 16B per thread) ----
    #pragma unroll
    for (int i = 0; i < 8; i++) {
        int u = tid + i * 256;
        int c = u >> 9, w = u & 511, r = w >> 3, cc = w & 7;
        uint32_t dst = sm_u + c * ACH + (uint32_t)(r * 128 + ((cc ^ (r & 7)) << 4));
        cp_async16(dst, g_q8 + ((size_t)(rowBase + r) << 9) + c * 128 + cc * 16);
    }
    asm volatile("cp.async.commit_group;\n");
    #pragma unroll
    for (int g = 0; g < 2; g++) {             // B slots 0,1
        int bnB = (bn0 + (g >> 2)) * 128;
        int kB = (g & 3) * 128;
        #pragma unroll
        for (int i = 0; i < 4; i++) {
            int r = lr + i * 32;
            uint32_t dst = sm_u + OFFB + g * BCH + (uint32_t)(r * 128 + ((lcc ^ (r & 7)) << 4));
            cp_async16(dst, gB + ((size_t)(bnB + r) << 9) + kB);
        }
        asm volatile("cp.async.commit_group;\n");
    }

    // ---- precomputed ldsm offsets ----
    int rA0 = wm * 32 + (lane & 15), rA1 = rA0 + 16;
    int rB0 = wn * 32 + (lane & 7) + ((lane >> 4) << 3), rB1 = rB0 + 16;
    uint32_t cA = (uint32_t)(lane >> 4);
    uint32_t cB = (uint32_t)((lane >> 3) & 1);
    uint32_t adA0[4], adA1[4], adB0[4], adB1[4];
    #pragma unroll
    for (int kk = 0; kk < 4; kk++) {
        adA0[kk] = (uint32_t)(rA0 * 128) + ((((uint32_t)(kk * 2) + cA) ^ (uint32_t)(rA0 & 7)) << 4);
        adA1[kk] = (uint32_t)(rA1 * 128) + ((((uint32_t)(kk * 2) + cA) ^ (uint32_t)(rA1 & 7)) << 4);
        adB0[kk] = (uint32_t)(rB0 * 128) + ((((uint32_t)(kk * 2) + cB) ^ (uint32_t)(rB0 & 7)) << 4);
        adB1[kk] = (uint32_t)(rB1 * 128) + ((((uint32_t)(kk * 2) + cB) ^ (uint32_t)(rB1 & 7)) << 4);
    }

    // ---- hoisted row betas ----
    float betaR[2][2];
    #pragma unroll
    for (int mt = 0; mt < 2; mt++)
        #pragma unroll
        for (int h = 0; h < 2; h++)
            betaR[mt][h] = __ldg(&g_beta[rowBase + wm * 32 + mt * 16 + (lane >> 2) + h * 8]);

    int acc[2][4][4];
    #pragma unroll
    for (int i = 0; i < 2; i++)
        #pragma unroll
        for (int j = 0; j < 4; j++)
            #pragma unroll
            for (int k = 0; k < 4; k++) acc[i][j][k] = 0;

    // ---- flat stage loop ----
    int sCur = 0, sPre = 2;
    int lastF = total - 1;
    #pragma unroll 1
    for (int f = 0; f < total; f++) {
        if (f < lastF) asm volatile("cp.async.wait_group 1;\n");
        else           asm volatile("cp.async.wait_group 0;\n");
        __syncthreads();
        int g = f + 2;
        if (g < total) {
            int bnB = (bn0 + (g >> 2)) * 128;
            int kB = (g & 3) * 128;
            #pragma unroll
            for (int i = 0; i < 4; i++) {
                int r = lr + i * 32;
                uint32_t dst = sm_u + OFFB + sPre * BCH + (uint32_t)(r * 128 + ((lcc ^ (r & 7)) << 4));
                cp_async16(dst, gB + ((size_t)(bnB + r) << 9) + kB);
            }
            asm volatile("cp.async.commit_group;\n");
        }

        uint32_t soA = sm_u + (uint32_t)((f & 3) * ACH);
        uint32_t soB = sm_u + OFFB + (uint32_t)(sCur * BCH);
        #pragma unroll
        for (int kk = 0; kk < 4; kk++) {
            uint32_t a[2][4], b[4][2];
            ldm_x4(a[0][0], a[0][1], a[0][2], a[0][3], soA + adA0[kk]);
            ldm_x4(a[1][0], a[1][1], a[1][2], a[1][3], soA + adA1[kk]);
            ldm_x4(b[0][0], b[0][1], b[1][0], b[1][1], soB + adB0[kk]);
            ldm_x4(b[2][0], b[2][1], b[3][0], b[3][1], soB + adB1[kk]);
            #pragma unroll
            for (int mt = 0; mt < 2; mt++)
                #pragma unroll
                for (int nt = 0; nt < 4; nt++)
                    mma_s8(acc[mt][nt], a[mt][0], a[mt][1], a[mt][2], a[mt][3],
                           b[nt][0], b[nt][1]);
        }
        if (++sCur == 3) sCur = 0;
        if (++sPre == 3) sPre = 0;

        if ((f & 3) == 3) {
            // ---- per-tile epilogue (barrier-free) ----
            int bn = bn0 + (f >> 2);
            bool diag = (bn == bm);
            bool isPos = (bn == bm + 16);
            float betaC[4][2];
            #pragma unroll
            for (int nt = 0; nt < 4; nt++)
                #pragma unroll
                for (int p = 0; p < 2; p++)
                    betaC[nt][p] = __ldg(&g_beta[bn * 128 + wn * 32 + nt * 8 + (lane & 3) * 2 + p]);

            float rowPart[2][2], colPart[4][2], pos_l = 0.0f;
            #pragma unroll
            for (int i = 0; i < 2; i++) rowPart[i][0] = rowPart[i][1] = 0.0f;
            #pragma unroll
            for (int i = 0; i < 4; i++) colPart[i][0] = colPart[i][1] = 0.0f;

            #pragma unroll
            for (int mt = 0; mt < 2; mt++)
                #pragma unroll
                for (int nt = 0; nt < 4; nt++)
                    #pragma unroll
                    for (int j = 0; j < 4; j++) {
                        float lg = __int2float_rn(acc[mt][nt][j]) *
                                   betaR[mt][j >> 1] * betaC[nt][j & 1];
                        float e = __expf(lg);
                        if (diag || isPos) {
                            int rl = hh * 64 + wm * 32 + mt * 16 + (lane >> 2) + (j >> 1) * 8;
                            int cl = wn * 32 + nt * 8 + (lane & 3) * 2 + (j & 1);
                            if (rl == cl) {
                                if (diag) e = 0.0f;
                                else pos_l += lg;
                            }
                        }
                        rowPart[mt][j >> 1] += e;
                        colPart[nt][j & 1] += e;
                        acc[mt][nt][j] = 0;
                    }

            #pragma unroll
            for (int mt = 0; mt < 2; mt++)
                #pragma unroll
                for (int q = 0; q < 2; q++) {
                    float v = rowPart[mt][q];
                    v += __shfl_xor_sync(0xffffffffu, v, 1);
                    v += __shfl_xor_sync(0xffffffffu, v, 2);
                    if ((lane & 3) == 0)
                        atomicAdd(&g_row_sum[rowBase + wm * 32 + mt * 16 + (lane >> 2) + q * 8], v);
                }
            if (!diag) {
                #pragma unroll
                for (int nt = 0; nt < 4; nt++)
                    #pragma unroll
                    for (int p = 0; p < 2; p++) {
                        float v = colPart[nt][p];
                        v += __shfl_xor_sync(0xffffffffu, v, 4);
                        v += __shfl_xor_sync(0xffffffffu, v, 8);
                        v += __shfl_xor_sync(0xffffffffu, v, 16);
                        if (lane < 4)
                            atomicAdd(&g_row_sum[bn * 128 + wn * 32 + nt * 8 + (lane & 3) * 2 + p], v);
                    }
            }
            if (isPos) {
                #pragma unroll
                for (int o = 16; o; o >>= 1) pos_l += __shfl_xor_sync(0xffffffffu, pos_l, o);
                if (lane == 0) atomicAdd(&g_pos_acc, pos_l);
            }
        }
    }

    // ---- finalize: last CTA computes the loss ----
    __threadfence();
    __syncthreads();
    if (tid == 0) {
        unsigned prev = atomicAdd(&g_ctr, 1u);
        s_last = (prev == (unsigned)(GRID_GEMM - 1)) ? 1 : 0;
    }
    __syncthreads();
    if (s_last) {
        __threadfence();
        float ls = 0.0f;
        #pragma unroll 1
        for (int r = tid; r < NROWS; r += 256) ls += logf(__ldcg(&g_row_sum[r]));
        #pragma unroll
        for (int o = 16; o; o >>= 1) ls += __shfl_xor_sync(0xffffffffu, ls, o);
        if (lane == 0) s_red[warp] = ls;
        __syncthreads();
        if (tid == 0) {
            float tot = 0.0f;
            #pragma unroll
            for (int i = 0; i < 8; i++) tot += s_red[i];
            float pos2 = __ldcg(&g_pos_acc) * 2.0f;
            out[0] = (tot - pos2) * (1.0f / (float)NROWS);
        }
    }
}

extern "C" void kernel_launch(void* const* d_in, const int* in_sizes, int n_in,
                              void* d_out, int out_size) {
    const float* z1 = (const float*)d_in[0];
    const float* z2 = (const float*)d_in[1];
    float* out = (float*)d_out;
    cudaFuncSetAttribute(k_persist, cudaFuncAttributeMaxDynamicSharedMemorySize, SMEM_DYN);
    k_normalize<<<NROWS, 128>>>(z1, z2);
    k_persist<<<GRID_GEMM, 256, SMEM_DYN>>>(out);
}

// round 12
// speedup vs baseline: 1.3394x; 1.0009x over previous
#include <cuda_runtime.h>
#include <cuda_bf16.h>
#include <math.h>
#include <stdint.h>

#define NROWS 4096
#define HALF_N 2048
#define DD 512

#define ACH 16384                  // A chunk: 128 rows x 128B
#define BCH 16384                  // B stage: 128 rows x 128B
#define OFFB 65536                 // B ring after 4 resident A chunks
#define SMEM_DYN (65536 + 4 * 16384 + 1024)
#define GRID_GEMM 144

// ---- device-global scratch ----
__device__ __align__(16) uint8_t g_q8[NROWS * DD];   // int8 quantized rows
__device__ float g_beta[NROWS];                      // sqrt(5)/|q_row|
__device__ float g_row_sum[NROWS];
__device__ float g_pos_acc;
__device__ unsigned int g_ctr;

// ============================================================
// K1: normalize -> int8 quantize; per-row beta; zero accumulators
// ============================================================
__global__ void k_normalize(const float* __restrict__ z1, const float* __restrict__ z2) {
    int row = blockIdx.x;
    const float* src = (row < HALF_N) ? (z1 + (size_t)row * DD)
                                      : (z2 + (size_t)(row - HALF_N) * DD);
    int t = threadIdx.x;
    float4 v = ((const float4*)src)[t];
    float ss = v.x * v.x + v.y * v.y + v.z * v.z + v.w * v.w;
    #pragma unroll
    for (int o = 16; o; o >>= 1) ss += __shfl_xor_sync(0xffffffffu, ss, o);

    __shared__ float warp_ss[4];
    __shared__ float s_inv;
    __shared__ int warp_qs[4];
    if ((t & 31) == 0) warp_ss[t >> 5] = ss;
    __syncthreads();
    if (t == 0) {
        float tot = warp_ss[0] + warp_ss[1] + warp_ss[2] + warp_ss[3];
        s_inv = 127.0f / fmaxf(sqrtf(tot), 1e-8f);
        g_row_sum[row] = 0.0f;
        if (row == 0) { g_pos_acc = 0.0f; g_ctr = 0u; }
    }
    __syncthreads();
    float inv = s_inv;
    int qa = __float2int_rn(fminf(fmaxf(v.x * inv, -127.0f), 127.0f));
    int qb = __float2int_rn(fminf(fmaxf(v.y * inv, -127.0f), 127.0f));
    int qc = __float2int_rn(fminf(fmaxf(v.z * inv, -127.0f), 127.0f));
    int qd = __float2int_rn(fminf(fmaxf(v.w * inv, -127.0f), 127.0f));
    uint32_t pk = (uint32_t)(qa & 0xFF) | ((uint32_t)(qb & 0xFF) << 8) |
                  ((uint32_t)(qc & 0xFF) << 16) | ((uint32_t)(qd & 0xFF) << 24);
    ((uint32_t*)(g_q8 + (size_t)row * DD))[t] = pk;

    int qs = qa * qa + qb * qb + qc * qc + qd * qd;
    #pragma unroll
    for (int o = 16; o; o >>= 1) qs += __shfl_xor_sync(0xffffffffu, qs, o);
    if ((t & 31) == 0) warp_qs[t >> 5] = qs;
    __syncthreads();
    if (t == 0) {
        int tq = warp_qs[0] + warp_qs[1] + warp_qs[2] + warp_qs[3];
        g_beta[row] = sqrtf(5.0f) * rsqrtf((float)tq);
    }
}

// ============================================================
// K2: persistent int8 IMMA GEMM, 128x128 tiles, 512 thr, 1 CTA/SM
// ============================================================
__device__ __forceinline__ void cp_async16(uint32_t saddr, const void* gptr) {
    asm volatile("cp.async.cg.shared.global [%0], [%1], 16;\n" :: "r"(saddr), "l"(gptr));
}
__device__ __forceinline__ void ldm_x4(uint32_t& r0, uint32_t& r1, uint32_t& r2, uint32_t& r3,
                                       uint32_t addr) {
    asm volatile("ldmatrix.sync.aligned.m8n8.x4.shared.b16 {%0,%1,%2,%3}, [%4];\n"
                 : "=r"(r0), "=r"(r1), "=r"(r2), "=r"(r3) : "r"(addr));
}
__device__ __forceinline__ void mma_s8(int* c, uint32_t a0, uint32_t a1, uint32_t a2,
                                       uint32_t a3, uint32_t b0, uint32_t b1) {
    asm volatile("mma.sync.aligned.m16n8k32.row.col.s32.s8.s8.s32 "
                 "{%0,%1,%2,%3}, {%4,%5,%6,%7}, {%8,%9}, {%0,%1,%2,%3};\n"
                 : "+r"(c[0]), "+r"(c[1]), "+r"(c[2]), "+r"(c[3])
                 : "r"(a0), "r"(a1), "r"(a2), "r"(a3), "r"(b0), "r"(b1));
}

__global__ void __launch_bounds__(512, 1) k_persist(float* __restrict__ out) {
    extern __shared__ uint8_t dsm_raw[];
    __shared__ float s_red[16];
    __shared__ int s_last;
    uint32_t raw_u = (uint32_t)__cvta_generic_to_shared(dsm_raw);
    uint32_t sm_u = (raw_u + 1023u) & ~1023u;

    // ---- CTA -> (bm, group-of-4-bn) ----
    int idx = blockIdx.x, bm = 0, gj = 0;
    #pragma unroll 1
    for (bm = 0; bm < 32; bm++) {
        int G = (32 - bm + 3) >> 2;
        if (idx < G) { gj = idx; break; }
        idx -= G;
    }
    int bn0 = bm + gj * 4;
    int n_tiles = 32 - bn0; if (n_tiles > 4) n_tiles = 4;
    int total = n_tiles * 4;
    int rowBase = bm * 128;

    int tid = threadIdx.x;
    int lane = tid & 31, warp = tid >> 5;
    int wm = warp >> 2, wn = warp & 3;        // 4x4 warp grid, 32x32 warp tiles

    // ---- loader geometry (B stage: 1024 x 16B, 2 per thread) ----
    int lr0 = tid >> 3, lc0 = tid & 7;
    int u1 = tid + 512;
    int lr1 = u1 >> 3, lc1 = u1 & 7;
    uint32_t wB0 = (uint32_t)(lr0 * 128 + ((lc0 ^ (lr0 & 7)) << 4));
    uint32_t wB1 = (uint32_t)(lr1 * 128 + ((lc1 ^ (lr1 & 7)) << 4));
    const uint8_t* gB0 = g_q8 + lc0 * 16;
    const uint8_t* gB1 = g_q8 + lc1 * 16;

    // ---- prologue: A resident (64KB = 4096 x 16B, 8 per thread) ----
    #pragma unroll
    for (int i = 0; i < 8; i++) {
        int u = tid + i * 512;
        int c = u >> 10, w = u & 1023, r = w >> 3, cc = w & 7;
        uint32_t dst = sm_u + c * ACH + (uint32_t)(r * 128 + ((cc ^ (r & 7)) << 4));
        cp_async16(dst, g_q8 + ((size_t)(rowBase + r) << 9) + c * 128 + cc * 16);
    }
    asm volatile("cp.async.commit_group;\n");
    #pragma unroll
    for (int g = 0; g < 3; g++) {             // B slots 0..2
        int bnB = (bn0 + (g >> 2)) * 128;
        int kB = (g & 3) * 128;
        uint32_t so = sm_u + OFFB + (uint32_t)((g & 3) * BCH);
        cp_async16(so + wB0, gB0 + ((size_t)(bnB + lr0) << 9) + kB);
        cp_async16(so + wB1, gB1 + ((size_t)(bnB + lr1) << 9) + kB);
        asm volatile("cp.async.commit_group;\n");
    }

    // ---- precomputed ldsm offsets ----
    int rA0 = wm * 32 + (lane & 15), rA1 = rA0 + 16;
    int rB0 = wn * 32 + (lane & 7) + ((lane >> 4) << 3), rB1 = rB0 + 16;
    uint32_t cA = (uint32_t)(lane >> 4);
    uint32_t cB = (uint32_t)((lane >> 3) & 1);
    uint32_t adA0[4], adA1[4], adB0[4], adB1[4];
    #pragma unroll
    for (int kk = 0; kk < 4; kk++) {
        adA0[kk] = (uint32_t)(rA0 * 128) + ((((uint32_t)(kk * 2) + cA) ^ (uint32_t)(rA0 & 7)) << 4);
        adA1[kk] = (uint32_t)(rA1 * 128) + ((((uint32_t)(kk * 2) + cA) ^ (uint32_t)(rA1 & 7)) << 4);
        adB0[kk] = (uint32_t)(rB0 * 128) + ((((uint32_t)(kk * 2) + cB) ^ (uint32_t)(rB0 & 7)) << 4);
        adB1[kk] = (uint32_t)(rB1 * 128) + ((((uint32_t)(kk * 2) + cB) ^ (uint32_t)(rB1 & 7)) << 4);
    }

    // ---- hoisted row betas ----
    float betaR[2][2];
    #pragma unroll
    for (int mt = 0; mt < 2; mt++)
        #pragma unroll
        for (int h = 0; h < 2; h++)
            betaR[mt][h] = __ldg(&g_beta[rowBase + wm * 32 + mt * 16 + (lane >> 2) + h * 8]);

    int acc[2][4][4];
    #pragma unroll
    for (int i = 0; i < 2; i++)
        #pragma unroll
        for (int j = 0; j < 4; j++)
            #pragma unroll
            for (int k = 0; k < 4; k++) acc[i][j][k] = 0;

    // ---- flat stage loop: stage f = tile (f>>2), K-chunk/B-slot (f&3-ish) ----
    #pragma unroll 1
    for (int f = 0; f < total; f++) {
        int rem = total - 1 - f;
        if (rem >= 2)      asm volatile("cp.async.wait_group 2;\n");
        else if (rem == 1) asm volatile("cp.async.wait_group 1;\n");
        else               asm volatile("cp.async.wait_group 0;\n");
        __syncthreads();
        int g = f + 3;
        if (g < total) {
            int bnB = (bn0 + (g >> 2)) * 128;
            int kB = (g & 3) * 128;
            uint32_t so = sm_u + OFFB + (uint32_t)((g & 3) * BCH);
            cp_async16(so + wB0, gB0 + ((size_t)(bnB + lr0) << 9) + kB);
            cp_async16(so + wB1, gB1 + ((size_t)(bnB + lr1) << 9) + kB);
            asm volatile("cp.async.commit_group;\n");
        }

        uint32_t soA = sm_u + (uint32_t)((f & 3) * ACH);
        uint32_t soB = sm_u + OFFB + (uint32_t)((f & 3) * BCH);
        #pragma unroll
        for (int kk = 0; kk < 4; kk++) {
            uint32_t a[2][4], b[4][2];
            ldm_x4(a[0][0], a[0][1], a[0][2], a[0][3], soA + adA0[kk]);
            ldm_x4(a[1][0], a[1][1], a[1][2], a[1][3], soA + adA1[kk]);
            ldm_x4(b[0][0], b[0][1], b[1][0], b[1][1], soB + adB0[kk]);
            ldm_x4(b[2][0], b[2][1], b[3][0], b[3][1], soB + adB1[kk]);
            #pragma unroll
            for (int mt = 0; mt < 2; mt++)
                #pragma unroll
                for (int nt = 0; nt < 4; nt++)
                    mma_s8(acc[mt][nt], a[mt][0], a[mt][1], a[mt][2], a[mt][3],
                           b[nt][0], b[nt][1]);
        }

        if ((f & 3) == 3) {
            // ---- per-tile epilogue (barrier-free) ----
            int bn = bn0 + (f >> 2);
            bool diag = (bn == bm);
            bool isPos = (bn == bm + 16);
            float betaC[4][2];
            #pragma unroll
            for (int nt = 0; nt < 4; nt++)
                #pragma unroll
                for (int p = 0; p < 2; p++)
                    betaC[nt][p] = __ldg(&g_beta[bn * 128 + wn * 32 + nt * 8 + (lane & 3) * 2 + p]);

            float rowPart[2][2], colPart[4][2], pos_l = 0.0f;
            #pragma unroll
            for (int i = 0; i < 2; i++) rowPart[i][0] = rowPart[i][1] = 0.0f;
            #pragma unroll
            for (int i = 0; i < 4; i++) colPart[i][0] = colPart[i][1] = 0.0f;

            #pragma unroll
            for (int mt = 0; mt < 2; mt++)
                #pragma unroll
                for (int nt = 0; nt < 4; nt++)
                    #pragma unroll
                    for (int j = 0; j < 4; j++) {
                        float lg = __int2float_rn(acc[mt][nt][j]) *
                                   betaR[mt][j >> 1] * betaC[nt][j & 1];
                        float e = __expf(lg);
                        if (diag || isPos) {
                            int rl = wm * 32 + mt * 16 + (lane >> 2) + (j >> 1) * 8;
                            int cl = wn * 32 + nt * 8 + (lane & 3) * 2 + (j & 1);
                            if (rl == cl) {
                                if (diag) e = 0.0f;
                                else pos_l += lg;
                            }
                        }
                        rowPart[mt][j >> 1] += e;
                        colPart[nt][j & 1] += e;
                        acc[mt][nt][j] = 0;
                    }

            #pragma unroll
            for (int mt = 0; mt < 2; mt++)
                #pragma unroll
                for (int q = 0; q < 2; q++) {
                    float v = rowPart[mt][q];
                    v += __shfl_xor_sync(0xffffffffu, v, 1);
                    v += __shfl_xor_sync(0xffffffffu, v, 2);
                    if ((lane & 3) == 0)
                        atomicAdd(&g_row_sum[rowBase + wm * 32 + mt * 16 + (lane >> 2) + q * 8], v);
                }
            if (!diag) {
                #pragma unroll
                for (int nt = 0; nt < 4; nt++)
                    #pragma unroll
                    for (int p = 0; p < 2; p++) {
                        float v = colPart[nt][p];
                        v += __shfl_xor_sync(0xffffffffu, v, 4);
                        v += __shfl_xor_sync(0xffffffffu, v, 8);
                        v += __shfl_xor_sync(0xffffffffu, v, 16);
                        if (lane < 4)
                            atomicAdd(&g_row_sum[bn * 128 + wn * 32 + nt * 8 + (lane & 3) * 2 + p], v);
                    }
            }
            if (isPos) {
                #pragma unroll
                for (int o = 16; o; o >>= 1) pos_l += __shfl_xor_sync(0xffffffffu, pos_l, o);
                if (lane == 0) atomicAdd(&g_pos_acc, pos_l);
            }
        }
    }

    // ---- finalize: last CTA computes the loss ----
    __threadfence();
    __syncthreads();
    if (tid == 0) {
        unsigned prev = atomicAdd(&g_ctr, 1u);
        s_last = (prev == (unsigned)(GRID_GEMM - 1)) ? 1 : 0;
    }
    __syncthreads();
    if (s_last) {
        __threadfence();
        float ls = 0.0f;
        #pragma unroll 1
        for (int r = tid; r < NROWS; r += 512) ls += logf(__ldcg(&g_row_sum[r]));
        #pragma unroll
        for (int o = 16; o; o >>= 1) ls += __shfl_xor_sync(0xffffffffu, ls, o);
        if (lane == 0) s_red[warp] = ls;
        __syncthreads();
        if (tid == 0) {
            float tot = 0.0f;
            #pragma unroll
            for (int i = 0; i < 16; i++) tot += s_red[i];
            float pos2 = __ldcg(&g_pos_acc) * 2.0f;
            out[0] = (tot - pos2) * (1.0f / (float)NROWS);
        }
    }
}

extern "C" void kernel_launch(void* const* d_in, const int* in_sizes, int n_in,
                              void* d_out, int out_size) {
    const float* z1 = (const float*)d_in[0];
    const float* z2 = (const float*)d_in[1];
    float* out = (float*)d_out;
    cudaFuncSetAttribute(k_persist, cudaFuncAttributeMaxDynamicSharedMemorySize, SMEM_DYN);
    k_normalize<<<NROWS, 128>>>(z1, z2);
    k_persist<<<GRID_GEMM, 512, SMEM_DYN>>>(out);
}

// round 13
// speedup vs baseline: 1.4130x; 1.0549x over previous
#include <cuda_runtime.h>
#include <cuda_bf16.h>
#include <math.h>
#include <stdint.h>

#define NROWS 4096
#define HALF_N 2048
#define DD 512

#define ACH 16384                  // A chunk: 128 rows x 128B (one K-quarter)
#define BST 32768                  // B stage: 128 rows x 256B (one K-half, 2 chunks)
#define OFFB 65536                 // B ring after 4 resident A chunks
#define SMEM_DYN (65536 + 3 * 32768 + 1024)
#define GRID_GEMM 144

// ---- device-global scratch ----
__device__ __align__(16) uint8_t g_q8[NROWS * DD];   // int8 quantized rows
__device__ float g_beta[NROWS];                      // sqrt(5)/|q_row|
__device__ float g_row_sum[NROWS];
__device__ float g_pos_acc;
__device__ unsigned int g_ctr;

// ============================================================
// K1: normalize -> int8 quantize; per-row beta; zero accumulators
// ============================================================
__global__ void k_normalize(const float* __restrict__ z1, const float* __restrict__ z2) {
    int row = blockIdx.x;
    const float* src = (row < HALF_N) ? (z1 + (size_t)row * DD)
                                      : (z2 + (size_t)(row - HALF_N) * DD);
    int t = threadIdx.x;
    float4 v = ((const float4*)src)[t];
    float ss = v.x * v.x + v.y * v.y + v.z * v.z + v.w * v.w;
    #pragma unroll
    for (int o = 16; o; o >>= 1) ss += __shfl_xor_sync(0xffffffffu, ss, o);

    __shared__ float warp_ss[4];
    __shared__ float s_inv;
    __shared__ int warp_qs[4];
    if ((t & 31) == 0) warp_ss[t >> 5] = ss;
    __syncthreads();
    if (t == 0) {
        float tot = warp_ss[0] + warp_ss[1] + warp_ss[2] + warp_ss[3];
        s_inv = 127.0f / fmaxf(sqrtf(tot), 1e-8f);
        g_row_sum[row] = 0.0f;
        if (row == 0) { g_pos_acc = 0.0f; g_ctr = 0u; }
    }
    __syncthreads();
    float inv = s_inv;
    int qa = __float2int_rn(fminf(fmaxf(v.x * inv, -127.0f), 127.0f));
    int qb = __float2int_rn(fminf(fmaxf(v.y * inv, -127.0f), 127.0f));
    int qc = __float2int_rn(fminf(fmaxf(v.z * inv, -127.0f), 127.0f));
    int qd = __float2int_rn(fminf(fmaxf(v.w * inv, -127.0f), 127.0f));
    uint32_t pk = (uint32_t)(qa & 0xFF) | ((uint32_t)(qb & 0xFF) << 8) |
                  ((uint32_t)(qc & 0xFF) << 16) | ((uint32_t)(qd & 0xFF) << 24);
    ((uint32_t*)(g_q8 + (size_t)row * DD))[t] = pk;

    int qs = qa * qa + qb * qb + qc * qc + qd * qd;
    #pragma unroll
    for (int o = 16; o; o >>= 1) qs += __shfl_xor_sync(0xffffffffu, qs, o);
    if ((t & 31) == 0) warp_qs[t >> 5] = qs;
    __syncthreads();
    if (t == 0) {
        int tq = warp_qs[0] + warp_qs[1] + warp_qs[2] + warp_qs[3];
        g_beta[row] = sqrtf(5.0f) * rsqrtf((float)tq);
    }
}

// ============================================================
// K2: persistent int8 IMMA, 128x128 tiles, 32KB K-half stages (8 barriers)
// ============================================================
__device__ __forceinline__ void cp_async16(uint32_t saddr, const void* gptr) {
    asm volatile("cp.async.cg.shared.global [%0], [%1], 16;\n" :: "r"(saddr), "l"(gptr));
}
__device__ __forceinline__ void ldm_x4(uint32_t& r0, uint32_t& r1, uint32_t& r2, uint32_t& r3,
                                       uint32_t addr) {
    asm volatile("ldmatrix.sync.aligned.m8n8.x4.shared.b16 {%0,%1,%2,%3}, [%4];\n"
                 : "=r"(r0), "=r"(r1), "=r"(r2), "=r"(r3) : "r"(addr));
}
__device__ __forceinline__ void mma_s8(int* c, uint32_t a0, uint32_t a1, uint32_t a2,
                                       uint32_t a3, uint32_t b0, uint32_t b1) {
    asm volatile("mma.sync.aligned.m16n8k32.row.col.s32.s8.s8.s32 "
                 "{%0,%1,%2,%3}, {%4,%5,%6,%7}, {%8,%9}, {%0,%1,%2,%3};\n"
                 : "+r"(c[0]), "+r"(c[1]), "+r"(c[2]), "+r"(c[3])
                 : "r"(a0), "r"(a1), "r"(a2), "r"(a3), "r"(b0), "r"(b1));
}

__global__ void __launch_bounds__(512, 1) k_persist(float* __restrict__ out) {
    extern __shared__ uint8_t dsm_raw[];
    __shared__ float s_red[16];
    __shared__ int s_last;
    uint32_t raw_u = (uint32_t)__cvta_generic_to_shared(dsm_raw);
    uint32_t sm_u = (raw_u + 1023u) & ~1023u;

    // ---- CTA -> (bm, group-of-4-bn) ----
    int idx = blockIdx.x, bm = 0, gj = 0;
    #pragma unroll 1
    for (bm = 0; bm < 32; bm++) {
        int G = (32 - bm + 3) >> 2;
        if (idx < G) { gj = idx; break; }
        idx -= G;
    }
    int bn0 = bm + gj * 4;
    int n_tiles = 32 - bn0; if (n_tiles > 4) n_tiles = 4;
    int total = n_tiles * 2;                  // 32KB K-half stages
    int rowBase = bm * 128;

    int tid = threadIdx.x;
    int lane = tid & 31, warp = tid >> 5;
    int wm = warp >> 2, wn = warp & 3;        // 4x4 warp grid, 32x32 warp tiles

    // ---- loader geometry: B stage = 2048 x 16B, 4 per thread ----
    // unit u: chunk = u>>10, r = (u>>3)&127, cc = u&7
    int lu[4], lru[4], lcu[4], lch[4];
    #pragma unroll
    for (int i = 0; i < 4; i++) {
        int u = tid + i * 512;
        lch[i] = u >> 10; lru[i] = (u >> 3) & 127; lcu[i] = u & 7;
        lu[i] = lru[i] * 128 + ((lcu[i] ^ (lru[i] & 7)) << 4) + lch[i] * 16384;
    }

    // ---- prologue: A resident (64KB, 8 x 16B per thread) ----
    #pragma unroll
    for (int i = 0; i < 8; i++) {
        int u = tid + i * 512;
        int c = u >> 10, w = u & 1023, r = w >> 3, cc = w & 7;
        uint32_t dst = sm_u + c * ACH + (uint32_t)(r * 128 + ((cc ^ (r & 7)) << 4));
        cp_async16(dst, g_q8 + ((size_t)(rowBase + r) << 9) + c * 128 + cc * 16);
    }
    asm volatile("cp.async.commit_group;\n");
    #pragma unroll
    for (int g = 0; g < 2; g++) {             // B stages 0,1 -> slots 0,1
        int bnB = (bn0 + (g >> 1)) * 128;
        int kOff = (g & 1) * 256;
        uint32_t so = sm_u + OFFB + (uint32_t)(g * BST);
        #pragma unroll
        for (int i = 0; i < 4; i++)
            cp_async16(so + (uint32_t)lu[i],
                       g_q8 + ((size_t)(bnB + lru[i]) << 9) + kOff + lch[i] * 128 + lcu[i] * 16);
        asm volatile("cp.async.commit_group;\n");
    }

    // ---- precomputed within-chunk ldsm offsets ----
    int rA0 = wm * 32 + (lane & 15), rA1 = rA0 + 16;
    int rB0 = wn * 32 + (lane & 7) + ((lane >> 4) << 3), rB1 = rB0 + 16;
    uint32_t cA = (uint32_t)(lane >> 4);
    uint32_t cB = (uint32_t)((lane >> 3) & 1);
    uint32_t adA0[4], adA1[4], adB0[4], adB1[4];
    #pragma unroll
    for (int kk = 0; kk < 4; kk++) {
        adA0[kk] = (uint32_t)(rA0 * 128) + ((((uint32_t)(kk * 2) + cA) ^ (uint32_t)(rA0 & 7)) << 4);
        adA1[kk] = (uint32_t)(rA1 * 128) + ((((uint32_t)(kk * 2) + cA) ^ (uint32_t)(rA1 & 7)) << 4);
        adB0[kk] = (uint32_t)(rB0 * 128) + ((((uint32_t)(kk * 2) + cB) ^ (uint32_t)(rB0 & 7)) << 4);
        adB1[kk] = (uint32_t)(rB1 * 128) + ((((uint32_t)(kk * 2) + cB) ^ (uint32_t)(rB1 & 7)) << 4);
    }

    // ---- hoisted row betas ----
    float betaR[2][2];
    #pragma unroll
    for (int mt = 0; mt < 2; mt++)
        #pragma unroll
        for (int h = 0; h < 2; h++)
            betaR[mt][h] = __ldg(&g_beta[rowBase + wm * 32 + mt * 16 + (lane >> 2) + h * 8]);

    int acc[2][4][4];
    #pragma unroll
    for (int i = 0; i < 2; i++)
        #pragma unroll
        for (int j = 0; j < 4; j++)
            #pragma unroll
            for (int k = 0; k < 4; k++) acc[i][j][k] = 0;

    // ---- stage loop: stage f = tile (f>>1), K-half (f&1), slot f%3 ----
    int sCur = 0, sPre = 2;
    int lastF = total - 1;
    #pragma unroll 1
    for (int f = 0; f < total; f++) {
        if (f < lastF) asm volatile("cp.async.wait_group 1;\n");
        else           asm volatile("cp.async.wait_group 0;\n");
        __syncthreads();
        int g = f + 2;
        if (g < total) {
            int bnB = (bn0 + (g >> 1)) * 128;
            int kOff = (g & 1) * 256;
            uint32_t so = sm_u + OFFB + (uint32_t)(sPre * BST);
            #pragma unroll
            for (int i = 0; i < 4; i++)
                cp_async16(so + (uint32_t)lu[i],
                           g_q8 + ((size_t)(bnB + lru[i]) << 9) + kOff + lch[i] * 128 + lcu[i] * 16);
            asm volatile("cp.async.commit_group;\n");
        }

        // 2 chunks of K per stage
        #pragma unroll
        for (int c = 0; c < 2; c++) {
            uint32_t soA = sm_u + (uint32_t)(((f & 1) * 2 + c) * ACH);
            uint32_t soB = sm_u + OFFB + (uint32_t)(sCur * BST + c * 16384);
            #pragma unroll
            for (int kk = 0; kk < 4; kk++) {
                uint32_t a[2][4], b[4][2];
                ldm_x4(a[0][0], a[0][1], a[0][2], a[0][3], soA + adA0[kk]);
                ldm_x4(a[1][0], a[1][1], a[1][2], a[1][3], soA + adA1[kk]);
                ldm_x4(b[0][0], b[0][1], b[1][0], b[1][1], soB + adB0[kk]);
                ldm_x4(b[2][0], b[2][1], b[3][0], b[3][1], soB + adB1[kk]);
                #pragma unroll
                for (int mt = 0; mt < 2; mt++)
                    #pragma unroll
                    for (int nt = 0; nt < 4; nt++)
                        mma_s8(acc[mt][nt], a[mt][0], a[mt][1], a[mt][2], a[mt][3],
                               b[nt][0], b[nt][1]);
            }
        }
        if (++sCur == 3) sCur = 0;
        if (++sPre == 3) sPre = 0;

        if ((f & 1) == 1) {
            // ---- per-tile epilogue (barrier-free) ----
            int bn = bn0 + (f >> 1);
            bool diag = (bn == bm);
            bool isPos = (bn == bm + 16);
            float betaC[4][2];
            #pragma unroll
            for (int nt = 0; nt < 4; nt++)
                #pragma unroll
                for (int p = 0; p < 2; p++)
                    betaC[nt][p] = __ldg(&g_beta[bn * 128 + wn * 32 + nt * 8 + (lane & 3) * 2 + p]);

            float rowPart[2][2], colPart[4][2], pos_l = 0.0f;
            #pragma unroll
            for (int i = 0; i < 2; i++) rowPart[i][0] = rowPart[i][1] = 0.0f;
            #pragma unroll
            for (int i = 0; i < 4; i++) colPart[i][0] = colPart[i][1] = 0.0f;

            #pragma unroll
            for (int mt = 0; mt < 2; mt++)
                #pragma unroll
                for (int nt = 0; nt < 4; nt++)
                    #pragma unroll
                    for (int j = 0; j < 4; j++) {
                        float lg = __int2float_rn(acc[mt][nt][j]) *
                                   betaR[mt][j >> 1] * betaC[nt][j & 1];
                        float e = __expf(lg);
                        if (diag || isPos) {
                            int rl = wm * 32 + mt * 16 + (lane >> 2) + (j >> 1) * 8;
                            int cl = wn * 32 + nt * 8 + (lane & 3) * 2 + (j & 1);
                            if (rl == cl) {
                                if (diag) e = 0.0f;
                                else pos_l += lg;
                            }
                        }
                        rowPart[mt][j >> 1] += e;
                        colPart[nt][j & 1] += e;
                        acc[mt][nt][j] = 0;
                    }

            #pragma unroll
            for (int mt = 0; mt < 2; mt++)
                #pragma unroll
                for (int q = 0; q < 2; q++) {
                    float v = rowPart[mt][q];
                    v += __shfl_xor_sync(0xffffffffu, v, 1);
                    v += __shfl_xor_sync(0xffffffffu, v, 2);
                    if ((lane & 3) == 0)
                        atomicAdd(&g_row_sum[rowBase + wm * 32 + mt * 16 + (lane >> 2) + q * 8], v);
                }
            if (!diag) {
                #pragma unroll
                for (int nt = 0; nt < 4; nt++)
                    #pragma unroll
                    for (int p = 0; p < 2; p++) {
                        float v = colPart[nt][p];
                        v += __shfl_xor_sync(0xffffffffu, v, 4);
                        v += __shfl_xor_sync(0xffffffffu, v, 8);
                        v += __shfl_xor_sync(0xffffffffu, v, 16);
                        if (lane < 4)
                            atomicAdd(&g_row_sum[bn * 128 + wn * 32 + nt * 8 + (lane & 3) * 2 + p], v);
                    }
            }
            if (isPos) {
                #pragma unroll
                for (int o = 16; o; o >>= 1) pos_l += __shfl_xor_sync(0xffffffffu, pos_l, o);
                if (lane == 0) atomicAdd(&g_pos_acc, pos_l);
            }
        }
    }

    // ---- finalize: last CTA computes the loss ----
    __threadfence();
    __syncthreads();
    if (tid == 0) {
        unsigned prev = atomicAdd(&g_ctr, 1u);
        s_last = (prev == (unsigned)(GRID_GEMM - 1)) ? 1 : 0;
    }
    __syncthreads();
    if (s_last) {
        __threadfence();
        float ls = 0.0f;
        #pragma unroll 1
        for (int r = tid; r < NROWS; r += 512) ls += logf(__ldcg(&g_row_sum[r]));
        #pragma unroll
        for (int o = 16; o; o >>= 1) ls += __shfl_xor_sync(0xffffffffu, ls, o);
        if (lane == 0) s_red[warp] = ls;
        __syncthreads();
        if (tid == 0) {
            float tot = 0.0f;
            #pragma unroll
            for (int i = 0; i < 16; i++) tot += s_red[i];
            float pos2 = __ldcg(&g_pos_acc) * 2.0f;
            out[0] = (tot - pos2) * (1.0f / (float)NROWS);
        }
    }
}

extern "C" void kernel_launch(void* const* d_in, const int* in_sizes, int n_in,
                              void* d_out, int out_size) {
    const float* z1 = (const float*)d_in[0];
    const float* z2 = (const float*)d_in[1];
    float* out = (float*)d_out;
    cudaFuncSetAttribute(k_persist, cudaFuncAttributeMaxDynamicSharedMemorySize, SMEM_DYN);
    k_normalize<<<NROWS, 128>>>(z1, z2);
    k_persist<<<GRID_GEMM, 512, SMEM_DYN>>>(out);
}